// round 3
// baseline (speedup 1.0000x reference)
#include <cuda_runtime.h>
#include <cstdint>

#define B_ 128
#define I_ 64
#define S_ 2048
#define CLUSTER 8
#define NTHR 512

// scratch: x transposed to [t][b][i]
__device__ float g_xT[(size_t)S_ * B_ * I_];

struct Smem {
  float in[192][8];          // k<64: x_t ; 64..192: h (cluster-shared)
  float iin[256][8];         // k<128: x_in ; else h_in (cluster-shared)
  float partial[16][64][8];  // gemv k-split partials
  float Wlin[8][129];
  float partialP[8][8][9];   // projection partials [kq][oo][row]
  float bo[64], bi[64], blin[8];
  unsigned long long mbar_iin;
  unsigned long long mbar_h;
};

__device__ __forceinline__ float tanh_ap(float x) {
  float y;
  asm("tanh.approx.f32 %0, %1;" : "=f"(y) : "f"(x));
  return y;
}
__device__ __forceinline__ float sigm_t(float x) {
  return fmaf(0.5f, tanh_ap(0.5f * x), 0.5f);
}
__device__ __forceinline__ void ffma2(unsigned long long& d, unsigned long long a,
                                      unsigned long long b) {
  asm("fma.rn.f32x2 %0, %1, %2, %0;" : "+l"(d) : "l"(a), "l"(b));
}
__device__ __forceinline__ unsigned long long dupf(float w) {
  unsigned long long r;
  asm("mov.b64 %0, {%1, %1};" : "=l"(r) : "f"(w));
  return r;
}
__device__ __forceinline__ uint32_t mapa_u32(uint32_t addr, uint32_t r) {
  uint32_t o;
  asm("mapa.shared::cluster.u32 %0, %1, %2;" : "=r"(o) : "r"(addr), "r"(r));
  return o;
}
__device__ __forceinline__ void stc128(uint32_t addr, float4 v) {
  asm volatile("st.shared::cluster.v4.f32 [%0], {%1,%2,%3,%4};" ::"r"(addr), "f"(v.x),
               "f"(v.y), "f"(v.z), "f"(v.w)
               : "memory");
}
__device__ __forceinline__ void arrive_remote(uint32_t local_mbar, uint32_t r) {
  uint32_t rem = mapa_u32(local_mbar, r);
  asm volatile("mbarrier.arrive.release.cluster.shared::cluster.b64 _, [%0];" ::"r"(rem)
               : "memory");
}
__device__ __forceinline__ void mbar_init(uint32_t mbar, uint32_t count) {
  asm volatile("mbarrier.init.shared.b64 [%0], %1;" ::"r"(mbar), "r"(count) : "memory");
}
__device__ __forceinline__ void wait_parity_cluster(uint32_t mbar, uint32_t parity) {
  asm volatile(
      "{\n\t.reg .pred P1;\n\t"
      "WL_%=:\n\t"
      "mbarrier.try_wait.parity.acquire.cluster.shared::cta.b64 P1, [%0], %1, 0x989680;\n\t"
      "@P1 bra.uni WD_%=;\n\t"
      "bra.uni WL_%=;\n\t"
      "WD_%=:\n\t}" ::"r"(mbar),
      "r"(parity)
      : "memory");
}
__device__ __forceinline__ void cluster_sync_() {
  asm volatile("barrier.cluster.arrive.aligned;" ::: "memory");
  asm volatile("barrier.cluster.wait.aligned;" ::: "memory");
}

__global__ void transpose_x(const float* __restrict__ x) {
  __shared__ float tile[32][33];
  int b = blockIdx.z;
  int i0 = blockIdx.y * 32;
  int t0 = blockIdx.x * 32;
  int tx = threadIdx.x, ty = threadIdx.y;
#pragma unroll
  for (int j = 0; j < 32; j += 8)
    tile[ty + j][tx] = x[(size_t)b * (I_ * S_) + (size_t)(i0 + ty + j) * S_ + t0 + tx];
  __syncthreads();
#pragma unroll
  for (int j = 0; j < 32; j += 8)
    g_xT[(size_t)(t0 + ty + j) * (B_ * I_) + b * I_ + i0 + tx] = tile[tx][ty + j];
}

// projection partial on threads 128..255 (4 slots each)
__device__ __forceinline__ void proj_partial4(Smem& sm, int tid) {
#pragma unroll
  for (int s = 0; s < 4; ++s) {
    int slot = (tid - 128) + 128 * s;
    int kq = slot >> 6, oo = (slot >> 3) & 7, row = slot & 7;
    int k0 = kq * 16;
    float pa = 0.f;
#pragma unroll
    for (int kk = 0; kk < 16; ++kk) pa += sm.Wlin[oo][k0 + kk] * sm.in[64 + k0 + kk][row];
    sm.partialP[kq][oo][row] = pa;
  }
}
__device__ __forceinline__ void proj_reduce_stg(Smem& sm, int ltid, int tout, int rank, int b0,
                                                float* __restrict__ out) {
  int row = ltid & 7, oo = ltid >> 3;
  float s = sm.blin[oo];
#pragma unroll
  for (int kq = 0; kq < 8; ++kq) s += sm.partialP[kq][oo][row];
  out[((size_t)(b0 + row) * S_ + tout) * 64 + rank * 8 + oo] = s;
}

__global__ void __launch_bounds__(NTHR, 1) __cluster_dims__(CLUSTER, 1, 1)
nlstm_kernel(const float* __restrict__ Wx_out, const float* __restrict__ Wh_out,
             const float* __restrict__ b_out, const float* __restrict__ Wx_in,
             const float* __restrict__ Wh_in, const float* __restrict__ b_in,
             const float* __restrict__ W_lin, const float* __restrict__ b_lin,
             float* __restrict__ out) {
  extern __shared__ __align__(16) char smem_raw[];
  Smem& sm = *reinterpret_cast<Smem*>(smem_raw);
  const int tid = threadIdx.x;
  const int warp = tid >> 5, lane = tid & 31;
  const int rank = blockIdx.x & (CLUSTER - 1);
  const int b0 = (blockIdx.x >> 3) * 8;

  // ---- init ----
  if (tid < 64) {
    int gcol = ((tid >> 4) << 7) + (rank << 4) + (tid & 15);
    sm.bo[tid] = b_out[gcol];
    sm.bi[tid] = b_in[gcol];
  }
  if (tid < 8) sm.blin[tid] = b_lin[rank * 8 + tid];
  for (int idx = tid; idx < 8 * 128; idx += NTHR)
    sm.Wlin[idx >> 7][idx & 127] = W_lin[(rank * 8 + (idx >> 7)) * 128 + (idx & 127)];
  for (int idx = tid; idx < 128 * 8; idx += NTHR) sm.in[64 + (idx >> 3)][idx & 7] = 0.f;
  {  // stage x(0)
    int k = tid & 63, row = tid >> 6;
    sm.in[k][row] = g_xT[(size_t)(b0 + row) * I_ + k];
  }
  const uint32_t mb_iin = (uint32_t)__cvta_generic_to_shared(&sm.mbar_iin);
  const uint32_t mb_h = (uint32_t)__cvta_generic_to_shared(&sm.mbar_h);
  if (tid == 0) {
    mbar_init(mb_iin, CLUSTER);
    mbar_init(mb_h, CLUSTER);
  }
  __syncthreads();
  cluster_sync_();

  // ---- register weights: warp = k-split, lane covers cols (lane, lane+32) ----
  float wOx[2][4], wOh[2][8], wI[2][16];
#pragma unroll
  for (int cg = 0; cg < 2; ++cg) {
    int c = cg * 32 + lane;
    int gcol = ((c >> 4) << 7) + (rank << 4) + (c & 15);
#pragma unroll
    for (int kk = 0; kk < 4; ++kk) wOx[cg][kk] = Wx_out[(warp * 4 + kk) * 512 + gcol];
#pragma unroll
    for (int kk = 0; kk < 8; ++kk) wOh[cg][kk] = Wh_out[(warp * 8 + kk) * 512 + gcol];
#pragma unroll
    for (int kk = 0; kk < 16; ++kk) {
      int k = warp * 16 + kk;
      wI[cg][kk] = (k < 128) ? Wx_in[k * 512 + gcol] : Wh_in[(k - 128) * 512 + gcol];
    }
  }

  const uint32_t iin_sh = (uint32_t)__cvta_generic_to_shared(&sm.iin[rank * 16][0]);
  const uint32_t h_sh = (uint32_t)__cvta_generic_to_shared(&sm.in[64 + rank * 16][0]);
  const char* iin_g = (const char*)&sm.iin[rank * 16][0];
  const char* h_g = (const char*)&sm.in[64 + rank * 16][0];

  float c_reg = 0.f, cn_reg = 0.f, o_save = 0.f;
  float2 xpf = make_float2(0.f, 0.f);

  for (int t = 0; t < S_; ++t) {
    // x(t+1) prefetch (warps 8-15), latency hidden behind the gemv
    if (tid >= 256 && t + 1 < S_)
      xpf = *reinterpret_cast<const float2*>(&g_xT[(size_t)(t + 1) * (B_ * I_) + b0 * I_ +
                                                   (tid - 256) * 2]);

    // ---- P1a: outer gemv, x-part (k 0..63) ----
    unsigned long long a00 = 0, a01 = 0, a02 = 0, a03 = 0;
    unsigned long long a10 = 0, a11 = 0, a12 = 0, a13 = 0;
    {
      const float* up = &sm.in[warp * 4][0];
#pragma unroll
      for (int kk = 0; kk < 4; ++kk) {
        ulonglong2 u01 = *reinterpret_cast<const ulonglong2*>(up + kk * 8);
        ulonglong2 u23 = *reinterpret_cast<const ulonglong2*>(up + kk * 8 + 4);
        unsigned long long w0 = dupf(wOx[0][kk]);
        ffma2(a00, w0, u01.x);
        ffma2(a01, w0, u01.y);
        ffma2(a02, w0, u23.x);
        ffma2(a03, w0, u23.y);
        unsigned long long w1 = dupf(wOx[1][kk]);
        ffma2(a10, w1, u01.x);
        ffma2(a11, w1, u01.y);
        ffma2(a12, w1, u23.x);
        ffma2(a13, w1, u23.y);
      }
    }
    // wait for h(t-1) arrival (hidden partially behind P1a)
    if (t != 0) wait_parity_cluster(mb_h, (t - 1) & 1);
    // ---- P1b: outer gemv, h-part (k 64..191) ----
    {
      const float* up = &sm.in[64 + warp * 8][0];
#pragma unroll
      for (int kk = 0; kk < 8; ++kk) {
        ulonglong2 u01 = *reinterpret_cast<const ulonglong2*>(up + kk * 8);
        ulonglong2 u23 = *reinterpret_cast<const ulonglong2*>(up + kk * 8 + 4);
        unsigned long long w0 = dupf(wOh[0][kk]);
        ffma2(a00, w0, u01.x);
        ffma2(a01, w0, u01.y);
        ffma2(a02, w0, u23.x);
        ffma2(a03, w0, u23.y);
        unsigned long long w1 = dupf(wOh[1][kk]);
        ffma2(a10, w1, u01.x);
        ffma2(a11, w1, u01.y);
        ffma2(a12, w1, u23.x);
        ffma2(a13, w1, u23.y);
      }
    }
    {
      ulonglong2* p = reinterpret_cast<ulonglong2*>(&sm.partial[warp][lane][0]);
      p[0] = make_ulonglong2(a00, a01);
      p[1] = make_ulonglong2(a02, a03);
      ulonglong2* q = reinterpret_cast<ulonglong2*>(&sm.partial[warp][32 + lane][0]);
      q[0] = make_ulonglong2(a10, a11);
      q[1] = make_ulonglong2(a12, a13);
    }
    __syncthreads();  // A

    // ---- P2: gate reduce/act/combine (w0-3) | proj partial h(t-1) (w4-7) ----
    if (tid < 128) {
      int jj = tid >> 3, row = tid & 7;
      float s0 = sm.bo[jj], s1 = sm.bo[16 + jj], s2 = sm.bo[32 + jj], s3 = sm.bo[48 + jj];
#pragma unroll
      for (int ks = 0; ks < 16; ++ks) {
        s0 += sm.partial[ks][jj][row];
        s1 += sm.partial[ks][16 + jj][row];
        s2 += sm.partial[ks][32 + jj][row];
        s3 += sm.partial[ks][48 + jj][row];
      }
      float iv = sigm_t(s0), fv = sigm_t(s1);
      o_save = sigm_t(s2);
      float gv = tanh_ap(s3);
      sm.iin[rank * 16 + jj][row] = iv * gv;          // x_in, local
      sm.iin[128 + rank * 16 + jj][row] = fv * c_reg; // h_in, local
    } else if (tid < 256) {
      if (t > 0) proj_partial4(sm, tid);
    }
    __syncthreads();  // B

    // ---- iin broadcast: 512 threads, 16B chunks to all ranks ----
    {
      int r = tid >> 6, j = tid & 63;
      uint32_t off = (j < 32) ? (uint32_t)(j * 16) : (uint32_t)(4096 + (j - 32) * 16);
      float4 v = *reinterpret_cast<const float4*>(iin_g + off);
      stc128(mapa_u32(iin_sh + off, r), v);
    }
    __syncthreads();  // E1
    if (tid < 8) arrive_remote(mb_iin, tid);
    wait_parity_cluster(mb_iin, t & 1);

    // ---- P3: inner gemv (k 0..255) ----
    {
      unsigned long long b00 = 0, b01 = 0, b02 = 0, b03 = 0;
      unsigned long long b10 = 0, b11 = 0, b12 = 0, b13 = 0;
      const float* up = &sm.iin[warp * 16][0];
#pragma unroll
      for (int kk = 0; kk < 16; ++kk) {
        ulonglong2 u01 = *reinterpret_cast<const ulonglong2*>(up + kk * 8);
        ulonglong2 u23 = *reinterpret_cast<const ulonglong2*>(up + kk * 8 + 4);
        unsigned long long w0 = dupf(wI[0][kk]);
        ffma2(b00, w0, u01.x);
        ffma2(b01, w0, u01.y);
        ffma2(b02, w0, u23.x);
        ffma2(b03, w0, u23.y);
        unsigned long long w1 = dupf(wI[1][kk]);
        ffma2(b10, w1, u01.x);
        ffma2(b11, w1, u01.y);
        ffma2(b12, w1, u23.x);
        ffma2(b13, w1, u23.y);
      }
      ulonglong2* p = reinterpret_cast<ulonglong2*>(&sm.partial[warp][lane][0]);
      p[0] = make_ulonglong2(b00, b01);
      p[1] = make_ulonglong2(b02, b03);
      ulonglong2* q = reinterpret_cast<ulonglong2*>(&sm.partial[warp][32 + lane][0]);
      q[0] = make_ulonglong2(b10, b11);
      q[1] = make_ulonglong2(b12, b13);
    }
    __syncthreads();  // C

    // ---- P4: inner reduce/state (w0-3) | proj reduce+STG (w4-5) | x stage (w8-15) ----
    if (tid < 128) {
      int jj = tid >> 3, row = tid & 7;
      float s0 = sm.bi[jj], s1 = sm.bi[16 + jj], s2 = sm.bi[32 + jj], s3 = sm.bi[48 + jj];
#pragma unroll
      for (int ks = 0; ks < 16; ++ks) {
        s0 += sm.partial[ks][jj][row];
        s1 += sm.partial[ks][16 + jj][row];
        s2 += sm.partial[ks][32 + jj][row];
        s3 += sm.partial[ks][48 + jj][row];
      }
      float ii = sigm_t(s0), ff = sigm_t(s1), o2 = sigm_t(s2), gg = tanh_ap(s3);
      cn_reg = ff * cn_reg + ii * gg;
      c_reg = o2 * tanh_ap(cn_reg);
      sm.in[64 + rank * 16 + jj][row] = o_save * tanh_ap(c_reg);  // h, local
    } else if (tid < 192) {
      if (t > 0) proj_reduce_stg(sm, tid - 128, t - 1, rank, b0, out);
    } else if (tid >= 256) {
      if (t + 1 < S_) {
        int idx = (tid - 256) * 2;
        sm.in[idx & 63][idx >> 6] = xpf.x;
        sm.in[(idx + 1) & 63][idx >> 6] = xpf.y;
      }
    }
    __syncthreads();  // D

    // ---- h broadcast: 256 threads ----
    if (tid < 256) {
      int r = tid >> 5, j = tid & 31;
      uint32_t off = (uint32_t)(j * 16);
      float4 v = *reinterpret_cast<const float4*>(h_g + off);
      stc128(mapa_u32(h_sh + off, r), v);
    }
    __syncthreads();  // E2
    if (tid < 8) arrive_remote(mb_h, tid);
  }

  // ---- epilogue: projection for t = S_-1 ----
  wait_parity_cluster(mb_h, (S_ - 1) & 1);
  if (tid >= 128 && tid < 256) proj_partial4(sm, tid);
  __syncthreads();
  if (tid >= 128 && tid < 192) proj_reduce_stg(sm, tid - 128, S_ - 1, rank, b0, out);
}

extern "C" void kernel_launch(void* const* d_in, const int* in_sizes, int n_in,
                              void* d_out, int out_size) {
  (void)in_sizes;
  (void)n_in;
  (void)out_size;
  cudaFuncSetAttribute(nlstm_kernel, cudaFuncAttributeMaxDynamicSharedMemorySize,
                       (int)sizeof(Smem));
  transpose_x<<<dim3(S_ / 32, I_ / 32, B_), dim3(32, 8)>>>((const float*)d_in[0]);
  nlstm_kernel<<<(B_ / 8) * CLUSTER, NTHR, sizeof(Smem)>>>(
      (const float*)d_in[1], (const float*)d_in[2], (const float*)d_in[3],
      (const float*)d_in[4], (const float*)d_in[5], (const float*)d_in[6],
      (const float*)d_in[7], (const float*)d_in[8], (float*)d_out);
}

// round 4
// speedup vs baseline: 1.1137x; 1.1137x over previous
#include <cuda_runtime.h>
#include <cstdint>

#define B_ 128
#define I_ 64
#define S_ 2048
#define CLUSTER 8
#define NTHR 256

// scratch: x transposed to [t][b][i]
__device__ float g_xT[(size_t)S_ * B_ * I_];

struct Smem {
  float in[192][8];         // k<64: x_t ; 64..192: h (cluster-shared)
  float iin[256][8];        // k<128: x_in ; else h_in (cluster-shared)
  float partial[8][64][8];  // gemv k-split partials
  float Wlin[8][129];
  float partialP[8][8][9];  // projection partials [kq][oo][row]
  float bo[64], bi[64], blin[8];
  unsigned long long mbar_iin;
  unsigned long long mbar_h;
};

__device__ __forceinline__ float tanh_ap(float x) {
  float y;
  asm("tanh.approx.f32 %0, %1;" : "=f"(y) : "f"(x));
  return y;
}
__device__ __forceinline__ float sigm_t(float x) {
  return fmaf(0.5f, tanh_ap(0.5f * x), 0.5f);
}
__device__ __forceinline__ void ffma2(unsigned long long& d, unsigned long long a,
                                      unsigned long long b) {
  asm("fma.rn.f32x2 %0, %1, %2, %0;" : "+l"(d) : "l"(a), "l"(b));
}
__device__ __forceinline__ unsigned long long dupf(float w) {
  unsigned long long r;
  asm("mov.b64 %0, {%1, %1};" : "=l"(r) : "f"(w));
  return r;
}
__device__ __forceinline__ uint32_t mapa_u32(uint32_t addr, uint32_t r) {
  uint32_t o;
  asm("mapa.shared::cluster.u32 %0, %1, %2;" : "=r"(o) : "r"(addr), "r"(r));
  return o;
}
__device__ __forceinline__ void stc128(uint32_t addr, float4 v) {
  asm volatile("st.shared::cluster.v4.f32 [%0], {%1,%2,%3,%4};" ::"r"(addr), "f"(v.x),
               "f"(v.y), "f"(v.z), "f"(v.w)
               : "memory");
}
__device__ __forceinline__ void arrive_remote(uint32_t local_mbar, uint32_t r) {
  uint32_t rem = mapa_u32(local_mbar, r);
  asm volatile("mbarrier.arrive.release.cluster.shared::cluster.b64 _, [%0];" ::"r"(rem)
               : "memory");
}
__device__ __forceinline__ void mbar_init(uint32_t mbar, uint32_t count) {
  asm volatile("mbarrier.init.shared.b64 [%0], %1;" ::"r"(mbar), "r"(count) : "memory");
}
__device__ __forceinline__ void wait_parity_cluster(uint32_t mbar, uint32_t parity) {
  asm volatile(
      "{\n\t.reg .pred P1;\n\t"
      "WL_%=:\n\t"
      "mbarrier.try_wait.parity.acquire.cluster.shared::cta.b64 P1, [%0], %1, 0x989680;\n\t"
      "@P1 bra.uni WD_%=;\n\t"
      "bra.uni WL_%=;\n\t"
      "WD_%=:\n\t}" ::"r"(mbar),
      "r"(parity)
      : "memory");
}
__device__ __forceinline__ void cluster_sync_() {
  asm volatile("barrier.cluster.arrive.aligned;" ::: "memory");
  asm volatile("barrier.cluster.wait.aligned;" ::: "memory");
}

__global__ void transpose_x(const float* __restrict__ x) {
  __shared__ float tile[32][33];
  int b = blockIdx.z;
  int i0 = blockIdx.y * 32;
  int t0 = blockIdx.x * 32;
  int tx = threadIdx.x, ty = threadIdx.y;
#pragma unroll
  for (int j = 0; j < 32; j += 8)
    tile[ty + j][tx] = x[(size_t)b * (I_ * S_) + (size_t)(i0 + ty + j) * S_ + t0 + tx];
  __syncthreads();
#pragma unroll
  for (int j = 0; j < 32; j += 8)
    g_xT[(size_t)(t0 + ty + j) * (B_ * I_) + b * I_ + i0 + tx] = tile[tx][ty + j];
}

// projection partial on threads 128..255 (4 slots each)
__device__ __forceinline__ void proj_partial4(Smem& sm, int tid) {
#pragma unroll
  for (int s = 0; s < 4; ++s) {
    int slot = (tid - 128) + 128 * s;
    int kq = slot >> 6, oo = (slot >> 3) & 7, row = slot & 7;
    int k0 = kq * 16;
    float pa = 0.f;
#pragma unroll
    for (int kk = 0; kk < 16; ++kk) pa += sm.Wlin[oo][k0 + kk] * sm.in[64 + k0 + kk][row];
    sm.partialP[kq][oo][row] = pa;
  }
}
__device__ __forceinline__ void proj_reduce_stg(Smem& sm, int ltid, int tout, int rank, int b0,
                                                float* __restrict__ out) {
  int row = ltid & 7, oo = ltid >> 3;
  float s = sm.blin[oo];
#pragma unroll
  for (int kq = 0; kq < 8; ++kq) s += sm.partialP[kq][oo][row];
  out[((size_t)(b0 + row) * S_ + tout) * 64 + rank * 8 + oo] = s;
}

__global__ void __launch_bounds__(NTHR, 1) __cluster_dims__(CLUSTER, 1, 1)
nlstm_kernel(const float* __restrict__ Wx_out, const float* __restrict__ Wh_out,
             const float* __restrict__ b_out, const float* __restrict__ Wx_in,
             const float* __restrict__ Wh_in, const float* __restrict__ b_in,
             const float* __restrict__ W_lin, const float* __restrict__ b_lin,
             float* __restrict__ out) {
  extern __shared__ __align__(16) char smem_raw[];
  Smem& sm = *reinterpret_cast<Smem*>(smem_raw);
  const int tid = threadIdx.x;
  const int warp = tid >> 5, lane = tid & 31;
  const int rank = blockIdx.x & (CLUSTER - 1);
  const int b0 = (blockIdx.x >> 3) * 8;

  // ---- init ----
  if (tid < 64) {
    int gcol = ((tid >> 4) << 7) + (rank << 4) + (tid & 15);
    sm.bo[tid] = b_out[gcol];
    sm.bi[tid] = b_in[gcol];
  }
  if (tid < 8) sm.blin[tid] = b_lin[rank * 8 + tid];
  for (int idx = tid; idx < 8 * 128; idx += NTHR)
    sm.Wlin[idx >> 7][idx & 127] = W_lin[(rank * 8 + (idx >> 7)) * 128 + (idx & 127)];
  for (int idx = tid; idx < 128 * 8; idx += NTHR) sm.in[64 + (idx >> 3)][idx & 7] = 0.f;
  for (int idx = tid; idx < 512; idx += NTHR)  // stage x(0)
    sm.in[idx & 63][idx >> 6] = g_xT[(size_t)(b0 + (idx >> 6)) * I_ + (idx & 63)];
  const uint32_t mb_iin = (uint32_t)__cvta_generic_to_shared(&sm.mbar_iin);
  const uint32_t mb_h = (uint32_t)__cvta_generic_to_shared(&sm.mbar_h);
  if (tid == 0) {
    mbar_init(mb_iin, CLUSTER);
    mbar_init(mb_h, CLUSTER);
  }
  __syncthreads();
  cluster_sync_();

  // ---- register weights: warp = k-split (8), lane covers cols (lane, lane+32) ----
  float wOx[2][8], wOh[2][16], wI[2][32];
#pragma unroll
  for (int cg = 0; cg < 2; ++cg) {
    int c = cg * 32 + lane;
    int gcol = ((c >> 4) << 7) + (rank << 4) + (c & 15);
#pragma unroll
    for (int kk = 0; kk < 8; ++kk) wOx[cg][kk] = Wx_out[(warp * 8 + kk) * 512 + gcol];
#pragma unroll
    for (int kk = 0; kk < 16; ++kk) wOh[cg][kk] = Wh_out[(warp * 16 + kk) * 512 + gcol];
#pragma unroll
    for (int kk = 0; kk < 32; ++kk) {
      int k = warp * 32 + kk;
      wI[cg][kk] = (k < 128) ? Wx_in[k * 512 + gcol] : Wh_in[(k - 128) * 512 + gcol];
    }
  }

  const uint32_t iin_sh = (uint32_t)__cvta_generic_to_shared(&sm.iin[rank * 16][0]);
  const uint32_t h_sh = (uint32_t)__cvta_generic_to_shared(&sm.in[64 + rank * 16][0]);
  const char* iin_g = (const char*)&sm.iin[rank * 16][0];
  const char* h_g = (const char*)&sm.in[64 + rank * 16][0];

  float c_reg = 0.f, cn_reg = 0.f, o_save = 0.f;
  float4 xpf = make_float4(0.f, 0.f, 0.f, 0.f);

  for (int t = 0; t < S_; ++t) {
    // x(t+1) prefetch (warps 4-7): 128 threads x float4 = 512 floats
    if (tid >= 128 && t + 1 < S_)
      xpf = *reinterpret_cast<const float4*>(
          &g_xT[(size_t)(t + 1) * (B_ * I_) + b0 * I_ + (tid - 128) * 4]);

    // ---- P1a: outer gemv, x-part (k 0..63) ----
    unsigned long long a00 = 0, a01 = 0, a02 = 0, a03 = 0;
    unsigned long long a10 = 0, a11 = 0, a12 = 0, a13 = 0;
    {
      const float* up = &sm.in[warp * 8][0];
#pragma unroll
      for (int kk = 0; kk < 8; ++kk) {
        ulonglong2 u01 = *reinterpret_cast<const ulonglong2*>(up + kk * 8);
        ulonglong2 u23 = *reinterpret_cast<const ulonglong2*>(up + kk * 8 + 4);
        unsigned long long w0 = dupf(wOx[0][kk]);
        ffma2(a00, w0, u01.x);
        ffma2(a01, w0, u01.y);
        ffma2(a02, w0, u23.x);
        ffma2(a03, w0, u23.y);
        unsigned long long w1 = dupf(wOx[1][kk]);
        ffma2(a10, w1, u01.x);
        ffma2(a11, w1, u01.y);
        ffma2(a12, w1, u23.x);
        ffma2(a13, w1, u23.y);
      }
    }
    // wait for h(t-1) arrival (partially hidden behind P1a)
    if (t != 0) wait_parity_cluster(mb_h, (t - 1) & 1);
    // ---- P1b: outer gemv, h-part (k 64..191) ----
    {
      const float* up = &sm.in[64 + warp * 16][0];
#pragma unroll
      for (int kk = 0; kk < 16; ++kk) {
        ulonglong2 u01 = *reinterpret_cast<const ulonglong2*>(up + kk * 8);
        ulonglong2 u23 = *reinterpret_cast<const ulonglong2*>(up + kk * 8 + 4);
        unsigned long long w0 = dupf(wOh[0][kk]);
        ffma2(a00, w0, u01.x);
        ffma2(a01, w0, u01.y);
        ffma2(a02, w0, u23.x);
        ffma2(a03, w0, u23.y);
        unsigned long long w1 = dupf(wOh[1][kk]);
        ffma2(a10, w1, u01.x);
        ffma2(a11, w1, u01.y);
        ffma2(a12, w1, u23.x);
        ffma2(a13, w1, u23.y);
      }
    }
    {
      ulonglong2* p = reinterpret_cast<ulonglong2*>(&sm.partial[warp][lane][0]);
      p[0] = make_ulonglong2(a00, a01);
      p[1] = make_ulonglong2(a02, a03);
      ulonglong2* q = reinterpret_cast<ulonglong2*>(&sm.partial[warp][32 + lane][0]);
      q[0] = make_ulonglong2(a10, a11);
      q[1] = make_ulonglong2(a12, a13);
    }
    __syncthreads();  // A

    // ---- P2: gate reduce/act/combine (w0-3) | proj partial h(t-1) (w4-7) ----
    if (tid < 128) {
      int jj = tid >> 3, row = tid & 7;
      float s0 = sm.bo[jj], s1 = sm.bo[16 + jj], s2 = sm.bo[32 + jj], s3 = sm.bo[48 + jj];
#pragma unroll
      for (int ks = 0; ks < 8; ++ks) {
        s0 += sm.partial[ks][jj][row];
        s1 += sm.partial[ks][16 + jj][row];
        s2 += sm.partial[ks][32 + jj][row];
        s3 += sm.partial[ks][48 + jj][row];
      }
      float iv = sigm_t(s0), fv = sigm_t(s1);
      o_save = sigm_t(s2);
      float gv = tanh_ap(s3);
      sm.iin[rank * 16 + jj][row] = iv * gv;           // x_in, local
      sm.iin[128 + rank * 16 + jj][row] = fv * c_reg;  // h_in, local
    } else {
      if (t > 0) proj_partial4(sm, tid);
    }
    __syncthreads();  // B

    // ---- iin broadcast: 256 threads; r = tid>>5, 2 chunks of 16B each ----
    {
      int r = tid >> 5, j = tid & 31;
      uint32_t off = (uint32_t)(j * 16);
      float4 vx = *reinterpret_cast<const float4*>(iin_g + off);
      float4 vh = *reinterpret_cast<const float4*>(iin_g + 4096 + off);
      uint32_t a = mapa_u32(iin_sh + off, r);
      stc128(a, vx);
      stc128(a + 4096, vh);
    }
    __syncthreads();  // E1
    if (tid < 8) arrive_remote(mb_iin, tid);
    wait_parity_cluster(mb_iin, t & 1);

    // ---- P3: inner gemv (k 0..255) ----
    {
      unsigned long long b00 = 0, b01 = 0, b02 = 0, b03 = 0;
      unsigned long long b10 = 0, b11 = 0, b12 = 0, b13 = 0;
      const float* up = &sm.iin[warp * 32][0];
#pragma unroll
      for (int kk = 0; kk < 32; ++kk) {
        ulonglong2 u01 = *reinterpret_cast<const ulonglong2*>(up + kk * 8);
        ulonglong2 u23 = *reinterpret_cast<const ulonglong2*>(up + kk * 8 + 4);
        unsigned long long w0 = dupf(wI[0][kk]);
        ffma2(b00, w0, u01.x);
        ffma2(b01, w0, u01.y);
        ffma2(b02, w0, u23.x);
        ffma2(b03, w0, u23.y);
        unsigned long long w1 = dupf(wI[1][kk]);
        ffma2(b10, w1, u01.x);
        ffma2(b11, w1, u01.y);
        ffma2(b12, w1, u23.x);
        ffma2(b13, w1, u23.y);
      }
      ulonglong2* p = reinterpret_cast<ulonglong2*>(&sm.partial[warp][lane][0]);
      p[0] = make_ulonglong2(b00, b01);
      p[1] = make_ulonglong2(b02, b03);
      ulonglong2* q = reinterpret_cast<ulonglong2*>(&sm.partial[warp][32 + lane][0]);
      q[0] = make_ulonglong2(b10, b11);
      q[1] = make_ulonglong2(b12, b13);
    }
    __syncthreads();  // C

    // ---- P4: inner reduce/state (w0-3) | proj reduce+STG, x stage (w4-7) ----
    if (tid < 128) {
      int jj = tid >> 3, row = tid & 7;
      float s0 = sm.bi[jj], s1 = sm.bi[16 + jj], s2 = sm.bi[32 + jj], s3 = sm.bi[48 + jj];
#pragma unroll
      for (int ks = 0; ks < 8; ++ks) {
        s0 += sm.partial[ks][jj][row];
        s1 += sm.partial[ks][16 + jj][row];
        s2 += sm.partial[ks][32 + jj][row];
        s3 += sm.partial[ks][48 + jj][row];
      }
      float ii = sigm_t(s0), ff = sigm_t(s1), o2 = sigm_t(s2), gg = tanh_ap(s3);
      cn_reg = ff * cn_reg + ii * gg;
      c_reg = o2 * tanh_ap(cn_reg);
      sm.in[64 + rank * 16 + jj][row] = o_save * tanh_ap(c_reg);  // h, local
    } else {
      if (t > 0 && tid < 192) proj_reduce_stg(sm, tid - 128, t - 1, rank, b0, out);
      if (t + 1 < S_) {
        int idx = (tid - 128) * 4;
        int row = idx >> 6, i = idx & 63;
        sm.in[i][row] = xpf.x;
        sm.in[i + 1][row] = xpf.y;
        sm.in[i + 2][row] = xpf.z;
        sm.in[i + 3][row] = xpf.w;
      }
    }
    __syncthreads();  // D

    // ---- h broadcast: 256 threads, 1 chunk each ----
    {
      int r = tid >> 5, j = tid & 31;
      uint32_t off = (uint32_t)(j * 16);
      float4 v = *reinterpret_cast<const float4*>(h_g + off);
      stc128(mapa_u32(h_sh + off, r), v);
    }
    __syncthreads();  // E2
    if (tid < 8) arrive_remote(mb_h, tid);
  }

  // ---- epilogue: projection for t = S_-1 ----
  wait_parity_cluster(mb_h, (S_ - 1) & 1);
  if (tid >= 128) proj_partial4(sm, tid);
  __syncthreads();
  if (tid >= 128 && tid < 192) proj_reduce_stg(sm, tid - 128, S_ - 1, rank, b0, out);
}

extern "C" void kernel_launch(void* const* d_in, const int* in_sizes, int n_in,
                              void* d_out, int out_size) {
  (void)in_sizes;
  (void)n_in;
  (void)out_size;
  cudaFuncSetAttribute(nlstm_kernel, cudaFuncAttributeMaxDynamicSharedMemorySize,
                       (int)sizeof(Smem));
  transpose_x<<<dim3(S_ / 32, I_ / 32, B_), dim3(32, 8)>>>((const float*)d_in[0]);
  nlstm_kernel<<<(B_ / 8) * CLUSTER, NTHR, sizeof(Smem)>>>(
      (const float*)d_in[1], (const float*)d_in[2], (const float*)d_in[3],
      (const float*)d_in[4], (const float*)d_in[5], (const float*)d_in[6],
      (const float*)d_in[7], (const float*)d_in[8], (float*)d_out);
}